// round 7
// baseline (speedup 1.0000x reference)
#include <cuda_runtime.h>
#include <cstdint>

#define VOCAB   128000
#define NV4     32000        // VOCAB / 4
#define NT      512
#define NWARP   (NT / 32)
#define NBIN    4096
#define CHUNK_V4 32          // 32 float4 = 128 elements per chunk
#define NCHUNK  (NV4 / CHUNK_V4)   // 1000
#define CAP     2048
#define K       32

// order-preserving float -> uint map
__device__ __forceinline__ unsigned f2u(float f) {
    unsigned b = __float_as_uint(f);
    return b ^ (unsigned)(((int)b >> 31) | 0x80000000);
}

// Accurate float32 log (fdlibm-style), ~1 ulp RELATIVE error even for x -> 1.
// Immune to --use_fast_math (no libm calls). Valid for normal x in (0, inf).
__device__ __forceinline__ float alog(float x) {
    int ix = __float_as_int(x);
    int k  = ((ix >> 23) & 0xFF) - 127;
    float m = __int_as_float((ix & 0x007FFFFF) | 0x3F800000);  // [1,2)
    if (m > 1.4142135f) { m *= 0.5f; k += 1; }                 // [sqrt1/2, sqrt2)
    float f = m - 1.0f;                   // exact
    float s = f / (2.0f + f);
    float z = s * s;
    float w = z * z;
    float t1 = w * (0.40000972152f + w * 0.24279078841f);
    float t2 = z * (0.66666662693f + w * 0.28498786688f);
    float R  = t2 + t1;
    float hfsq = 0.5f * f * f;
    float kf = (float)k;
    // k*ln2_hi - ((hfsq - (s*(hfsq+R) + k*ln2_lo)) - f)
    return kf * 0.69313812256f - ((hfsq - (s * (hfsq + R) + kf * 9.0580006145e-06f)) - f);
}

__device__ __forceinline__ unsigned key_u(float r, float p) {
    return f2u(alog(r) / p);
}

__global__ __launch_bounds__(NT, 2)
void topk_sample_kernel(const float* __restrict__ probs,
                        const float* __restrict__ rnd,
                        float* __restrict__ out)
{
    __shared__ unsigned int hist[NBIN];
    __shared__ unsigned int chunk_max[NCHUNK];
    __shared__ unsigned long long cand[CAP];
    __shared__ unsigned int part[NT];
    __shared__ unsigned int sh_thresh;
    __shared__ unsigned int sh_count;

    const int row = blockIdx.x;
    const int tid = threadIdx.x;
    const float4* __restrict__ p4 = (const float4*)(probs + (size_t)row * VOCAB);
    const float4* __restrict__ r4 = (const float4*)(rnd   + (size_t)row * VOCAB);

    for (int i = tid; i < NBIN; i += NT)   hist[i] = 0;
    for (int i = tid; i < NCHUNK; i += NT) chunk_max[i] = 0;
    if (tid == 0) sh_count = 0;
    __syncthreads();

    // ---------------- Pass 1: histogram + per-chunk max ----------------
    for (int vi = tid; vi < NV4; vi += NT) {
        float4 p = p4[vi];
        float4 r = r4[vi];
        unsigned u0 = key_u(r.x, p.x);
        unsigned u1 = key_u(r.y, p.y);
        unsigned u2 = key_u(r.z, p.z);
        unsigned u3 = key_u(r.w, p.w);
        atomicAdd(&hist[u0 >> 20], 1u);
        atomicAdd(&hist[u1 >> 20], 1u);
        atomicAdd(&hist[u2 >> 20], 1u);
        atomicAdd(&hist[u3 >> 20], 1u);
        unsigned m = max(max(u0, u1), max(u2, u3));
        // a warp's 32 consecutive vi fall in exactly one 32-aligned chunk
        m = __reduce_max_sync(0xFFFFFFFFu, m);
        if ((tid & 31) == 0) atomicMax(&chunk_max[vi >> 5], m);
    }
    __syncthreads();

    // ---------------- Cutoff bin: max b such that count(>= bin b) >= K ----------------
    {
        unsigned s = 0;
        #pragma unroll
        for (int j = 0; j < NBIN / NT; j++) s += hist[tid * (NBIN / NT) + j];
        part[tid] = s;
    }
    __syncthreads();
    if (tid == 0) {
        unsigned acc = 0;
        for (int t = NT - 1; t >= 0; --t) { unsigned tmp = part[t]; part[t] = acc; acc += tmp; }
    }
    __syncthreads();
    {
        unsigned above = part[tid];   // count in bins strictly above this thread's 8-bin block
        if (above < K) {
            unsigned acc = above;
            for (int j = NBIN / NT - 1; j >= 0; --j) {
                unsigned c = hist[tid * (NBIN / NT) + j];
                if (acc < K && acc + c >= K) {
                    sh_thresh = ((unsigned)(tid * (NBIN / NT) + j)) << 20;  // single writer
                }
                acc += c;
            }
        }
    }
    __syncthreads();
    const unsigned thresh = sh_thresh;

    // ---------------- Pass 2: gather candidates from surviving chunks ----------------
    {
        const int warp = tid >> 5, lane = tid & 31;
        for (int c = warp; c < NCHUNK; c += NWARP) {
            if (chunk_max[c] >= thresh) {
                int vi = c * CHUNK_V4 + lane;
                float4 p = p4[vi];
                float4 r = r4[vi];
                unsigned u[4];
                u[0] = key_u(r.x, p.x);
                u[1] = key_u(r.y, p.y);
                u[2] = key_u(r.z, p.z);
                u[3] = key_u(r.w, p.w);
                int base = vi * 4;
                #pragma unroll
                for (int e = 0; e < 4; e++) {
                    if (u[e] >= thresh) {
                        unsigned pos = atomicAdd(&sh_count, 1u);
                        if (pos < CAP) {
                            // pack: key desc primary, index asc on ties (matches lax.top_k)
                            cand[pos] = ((unsigned long long)u[e] << 32)
                                      | (unsigned)(VOCAB - 1 - (base + e));
                        }
                    }
                }
            }
        }
    }
    __syncthreads();

    // ---------------- Exact rank among candidates, emit top-K ----------------
    int C = (int)min(sh_count, (unsigned)CAP);
    for (int i = tid; i < C; i += NT) {
        unsigned long long mine = cand[i];
        int rank = 0;
        for (int j = 0; j < C; j++) rank += (cand[j] > mine);
        if (rank < K) {
            int idx = (int)(VOCAB - 1 - (unsigned)(mine & 0xFFFFFFFFu));
            out[row * K + rank] = (float)idx;   // output as float32 (__output__ dtype)
        }
    }
}

extern "C" void kernel_launch(void* const* d_in, const int* in_sizes, int n_in,
                              void* d_out, int out_size)
{
    const float* probs = (const float*)d_in[0];
    const float* rnd   = (const float*)d_in[1];
    float* out = (float*)d_out;
    int B = in_sizes[0] / VOCAB;
    topk_sample_kernel<<<B, NT>>>(probs, rnd, out);
}

// round 8
// speedup vs baseline: 1.4539x; 1.4539x over previous
#include <cuda_runtime.h>
#include <cstdint>

#define VOCAB   128000
#define NV4     32000        // VOCAB / 4
#define NT      512
#define NWARP   (NT / 32)
#define NBIN    4096
#define CHUNK_V4 32          // 32 float4 = 128 elements per chunk
#define NCHUNK  (NV4 / CHUNK_V4)   // 1000
#define CAP     2048
#define K       32

// order-preserving float -> uint map
__device__ __forceinline__ unsigned f2u(float f) {
    unsigned b = __float_as_uint(f);
    return b ^ (unsigned)(((int)b >> 31) | 0x80000000);
}

// Accurate float32 log (fdlibm-style), ~1 ulp RELATIVE error even for x -> 1.
// PROVEN (rel_err 0.0) to reproduce the reference ordering — do not modify.
__device__ __forceinline__ float alog(float x) {
    int ix = __float_as_int(x);
    int k  = ((ix >> 23) & 0xFF) - 127;
    float m = __int_as_float((ix & 0x007FFFFF) | 0x3F800000);  // [1,2)
    if (m > 1.4142135f) { m *= 0.5f; k += 1; }                 // [sqrt1/2, sqrt2)
    float f = m - 1.0f;                   // exact
    float s = f / (2.0f + f);
    float z = s * s;
    float w = z * z;
    float t1 = w * (0.40000972152f + w * 0.24279078841f);
    float t2 = z * (0.66666662693f + w * 0.28498786688f);
    float R  = t2 + t1;
    float hfsq = 0.5f * f * f;
    float kf = (float)k;
    return kf * 0.69313812256f - ((hfsq - (s * (hfsq + R) + kf * 9.0580006145e-06f)) - f);
}

// Exact key (pass 2 / ranking) — identical expression to the passing kernel.
__device__ __forceinline__ unsigned key_u(float r, float p) {
    return f2u(alog(r) / p);
}

// Cheap surrogate key for pass-1 binning. For all possible top-K contenders
// (which necessarily have r >= 1-7e-4), takes the polynomial branch with
// <= ~4e-7 RELATIVE error vs the exact key -> deviation of a few ulps in
// u-space, covered by a one-bin threshold margin. Elsewhere __logf's 3.6e-7
// absolute error is harmless (those elements are far below the cutoff).
__device__ __forceinline__ unsigned key_u_fast(float r, float p) {
    float f  = r - 1.0f;                       // exact
    float lp = f * __fmaf_rn(-0.5f, f, 1.0f);  // log1p(f), rel err ~ f^2/3
    float lf = 0.69314718056f * __logf(r);     // uses log2 intrinsic; abs err ~3.6e-7
    float lk = (f > -1e-3f) ? lp : lf;
    return f2u(__fdividef(lk, p));
}

__global__ __launch_bounds__(NT, 3)
void topk_sample_kernel(const float* __restrict__ probs,
                        const float* __restrict__ rnd,
                        float* __restrict__ out)
{
    __shared__ unsigned int hist[NBIN];
    __shared__ unsigned int chunk_max[NCHUNK];
    __shared__ unsigned long long cand[CAP];
    __shared__ unsigned int part[NT];
    __shared__ unsigned int sh_thresh;
    __shared__ unsigned int sh_count;

    const int row = blockIdx.x;
    const int tid = threadIdx.x;
    const float4* __restrict__ p4 = (const float4*)(probs + (size_t)row * VOCAB);
    const float4* __restrict__ r4 = (const float4*)(rnd   + (size_t)row * VOCAB);

    for (int i = tid; i < NBIN; i += NT)   hist[i] = 0;
    for (int i = tid; i < NCHUNK; i += NT) chunk_max[i] = 0;
    if (tid == 0) sh_count = 0;
    __syncthreads();

    // ---------------- Pass 1: surrogate histogram + per-chunk max ----------------
    #pragma unroll 2
    for (int vi = tid; vi < NV4; vi += NT) {
        float4 p = p4[vi];
        float4 r = r4[vi];
        unsigned u0 = key_u_fast(r.x, p.x);
        unsigned u1 = key_u_fast(r.y, p.y);
        unsigned u2 = key_u_fast(r.z, p.z);
        unsigned u3 = key_u_fast(r.w, p.w);
        atomicAdd(&hist[u0 >> 20], 1u);
        atomicAdd(&hist[u1 >> 20], 1u);
        atomicAdd(&hist[u2 >> 20], 1u);
        atomicAdd(&hist[u3 >> 20], 1u);
        unsigned m = max(max(u0, u1), max(u2, u3));
        // a warp's 32 consecutive vi fall in exactly one 32-aligned chunk
        m = __reduce_max_sync(0xFFFFFFFFu, m);
        if ((tid & 31) == 0) atomicMax(&chunk_max[vi >> 5], m);
    }
    __syncthreads();

    // ---------------- Cutoff bin: max b such that count(>= bin b) >= K ----------------
    {
        unsigned s = 0;
        #pragma unroll
        for (int j = 0; j < NBIN / NT; j++) s += hist[tid * (NBIN / NT) + j];
        part[tid] = s;
    }
    __syncthreads();
    if (tid == 0) {
        unsigned acc = 0;
        for (int t = NT - 1; t >= 0; --t) { unsigned tmp = part[t]; part[t] = acc; acc += tmp; }
    }
    __syncthreads();
    {
        unsigned above = part[tid];   // count in bins strictly above this thread's 8-bin block
        if (above < K) {
            unsigned acc = above;
            for (int j = NBIN / NT - 1; j >= 0; --j) {
                unsigned c = hist[tid * (NBIN / NT) + j];
                if (acc < K && acc + c >= K) {
                    sh_thresh = ((unsigned)(tid * (NBIN / NT) + j)) << 20;  // single writer
                }
                acc += c;
            }
        }
    }
    __syncthreads();
    // Lower by one full bin: covers surrogate-vs-exact deviation (few ulps)
    // on both the threshold location and per-element membership/chunk-max.
    const unsigned tbin = sh_thresh;
    const unsigned thresh = (tbin >= (1u << 20)) ? (tbin - (1u << 20)) : 0u;

    // ---------------- Pass 2: gather candidates (EXACT keys) from surviving chunks ----------------
    {
        const int warp = tid >> 5, lane = tid & 31;
        for (int c = warp; c < NCHUNK; c += NWARP) {
            if (chunk_max[c] >= thresh) {
                int vi = c * CHUNK_V4 + lane;
                float4 p = p4[vi];
                float4 r = r4[vi];
                unsigned u[4];
                u[0] = key_u(r.x, p.x);
                u[1] = key_u(r.y, p.y);
                u[2] = key_u(r.z, p.z);
                u[3] = key_u(r.w, p.w);
                int base = vi * 4;
                #pragma unroll
                for (int e = 0; e < 4; e++) {
                    if (u[e] >= thresh) {
                        unsigned pos = atomicAdd(&sh_count, 1u);
                        if (pos < CAP) {
                            // pack: key desc primary, index asc on ties (matches lax.top_k)
                            cand[pos] = ((unsigned long long)u[e] << 32)
                                      | (unsigned)(VOCAB - 1 - (base + e));
                        }
                    }
                }
            }
        }
    }
    __syncthreads();

    // ---------------- Exact rank among candidates, emit top-K ----------------
    int C = (int)min(sh_count, (unsigned)CAP);
    for (int i = tid; i < C; i += NT) {
        unsigned long long mine = cand[i];
        int rank = 0;
        for (int j = 0; j < C; j++) rank += (cand[j] > mine);
        if (rank < K) {
            int idx = (int)(VOCAB - 1 - (unsigned)(mine & 0xFFFFFFFFu));
            out[row * K + rank] = (float)idx;   // output as float32 (__output__ dtype)
        }
    }
}

extern "C" void kernel_launch(void* const* d_in, const int* in_sizes, int n_in,
                              void* d_out, int out_size)
{
    const float* probs = (const float*)d_in[0];
    const float* rnd   = (const float*)d_in[1];
    float* out = (float*)d_out;
    int B = in_sizes[0] / VOCAB;
    topk_sample_kernel<<<B, NT>>>(probs, rnd, out);
}